// round 3
// baseline (speedup 1.0000x reference)
#include <cuda_runtime.h>
#include <cstdint>

#define B    32
#define NN   2000
#define TD   384
#define E    64
#define TT   24
#define DD   16

#define BRR  64      // query rows per CTA
#define BCC  32      // kv rows per tile
#define NT   63      // ceil(NN/BCC)
#define KST  68      // k row stride (floats): stride%32==4 -> conflict-free LDS.128
#define VST  384     // v row stride
#define PST  66      // p row stride in u64 (64 data + 2 pad)
#define OST  388     // stage row stride (floats)
#define OST4 97

// attn smem layout (floats)
#define O_Q  0                         // 64*64        = 4096
#define O_K  4096                      // 3 * 32*68    = 6528
#define O_V  10624                     // 3 * 32*384   = 36864
#define O_P  47488                     // 32*66 u64    = 4224 floats
#define O_L  51712                     // 64 floats
#define SM_FLOATS 51776
#define SM_BYTES (SM_FLOATS*4)         // 207104 B

#define K1_ROWS 64
#define K1_SM_FLOATS (K1_ROWS*TD + K1_ROWS*128 + 128)
#define K1_SM_BYTES (K1_SM_FLOATS*4)   // 131584 B

typedef unsigned long long u64;

// scratch (device globals: the sanctioned no-alloc path)
__device__ float g_q1[B*NN*E];   // 16 MB
__device__ float g_k1[B*NN*E];   // 16 MB

// ---------- packed f32x2 helpers ----------
__device__ __forceinline__ u64 pack2(float a, float b){
    u64 r; asm("mov.b64 %0,{%1,%2};" : "=l"(r) : "f"(a), "f"(b)); return r;
}
__device__ __forceinline__ void ffma2(u64 &d, u64 a, u64 b){
    asm("fma.rn.f32x2 %0,%1,%2,%0;" : "+l"(d) : "l"(a), "l"(b));
}
__device__ __forceinline__ float2 unpack2(u64 v){
    float2 r; asm("mov.b64 {%0,%1},%2;" : "=f"(r.x), "=f"(r.y) : "l"(v)); return r;
}
__device__ __forceinline__ unsigned smaddr(const void* p){
    return (unsigned)__cvta_generic_to_shared(p);
}
__device__ __forceinline__ void cpa16(unsigned d, const void* s){
    asm volatile("cp.async.cg.shared.global [%0],[%1],16;" :: "r"(d), "l"(s));
}

// ============================================================
// Kernel 1: q1 = LN(xf@Wq + bq), k1 = LN(xf@Wk + bk)
// 64 rows/CTA, 512 threads. grp = tid>>6: bit2 = isK, bits[0:1] = row quarter.
// Each thread: one output column x 16 rows.
// ============================================================
__global__ __launch_bounds__(512, 1) void qk_ln_kernel(
    const float* __restrict__ x,
    const float* __restrict__ Wq, const float* __restrict__ bq,
    const float* __restrict__ Wk, const float* __restrict__ bk,
    const float* __restrict__ g0, const float* __restrict__ beta0,
    const float* __restrict__ g1, const float* __restrict__ beta1)
{
    extern __shared__ float sm1[];
    float* xs = sm1;                    // 64*384
    float* qk = sm1 + K1_ROWS*TD;       // 64*128
    float* st = qk + K1_ROWS*128;       // 128
    const int tid = threadIdx.x;
    const long base = (long)blockIdx.x * K1_ROWS;   // 1000 CTAs exact

    const float4* xp4 = (const float4*)(x + base*TD);
#pragma unroll
    for (int i = 0; i < 12; i++) ((float4*)xs)[tid + i*512] = xp4[tid + i*512];
    __syncthreads();

    const int col = tid & 63;
    const int grp = tid >> 6;
    const int isK = grp >> 2;
    const int r0  = (grp & 3) * 16;
    const float* __restrict__ W = isK ? Wk : Wq;

    u64 acc2[16];
#pragma unroll
    for (int r = 0; r < 16; r++) acc2[r] = 0ull;

    for (int i4 = 0; i4 < 96; i4++) {
        float w0 = W[(4*i4+0)*E + col];
        float w1 = W[(4*i4+1)*E + col];
        float w2 = W[(4*i4+2)*E + col];
        float w3 = W[(4*i4+3)*E + col];
        u64 wa = pack2(w0, w1), wb = pack2(w2, w3);
#pragma unroll
        for (int r = 0; r < 16; r++) {
            ulonglong2 xv = ((const ulonglong2*)(xs + (r0 + r)*TD))[i4];  // broadcast
            ffma2(acc2[r], xv.x, wa);
            ffma2(acc2[r], xv.y, wb);
        }
    }
    const float bias = isK ? bk[col] : bq[col];
#pragma unroll
    for (int r = 0; r < 16; r++) {
        float2 f = unpack2(acc2[r]);
        qk[(r0 + r)*128 + isK*64 + col] = f.x + f.y + bias;
    }
    __syncthreads();

    if (tid < 128) {
        int r = tid & 63, h = tid >> 6;
        const float* v = qk + r*128 + h*64;
        float s = 0.f, s2 = 0.f;
#pragma unroll
        for (int j = 0; j < 64; j++) { float t = v[(j + r) & 63]; s += t; s2 += t*t; }
        float mu = s * (1.f/64.f);
        float var = s2 * (1.f/64.f) - mu*mu;
        st[h*64 + r] = mu;
        // pack rsqrt into same buffer shifted: store separately below
        st[h*64 + r] = mu;  // mu
        qk[K1_ROWS*128 - 1];  // no-op
        // store rs in second half of st via reuse: st has 128 floats; use two arrays:
    }
    __syncthreads();
    // recompute rs from mu is cheap but we need var; do stats in one pass with two smem arrays:
    // (handled below — st holds mu; rs recomputed here by same threads into qk tail is avoided)
    // Instead: redo properly with dedicated second buffer region inside st:
    __shared__ float rs_sh[128];
    if (tid < 128) {
        int r = tid & 63, h = tid >> 6;
        const float* v = qk + r*128 + h*64;
        float s2 = 0.f; float mu = st[h*64 + r];
#pragma unroll
        for (int j = 0; j < 64; j++) { float t = v[(j + r) & 63] - mu; s2 += t*t; }
        rs_sh[h*64 + r] = rsqrtf(s2 * (1.f/64.f) + 1e-5f);
    }
    __syncthreads();

    const float gg = isK ? g1[col] : g0[col];
    const float bb = isK ? beta1[col] : beta0[col];
    float* __restrict__ outp = isK ? g_k1 : g_q1;
#pragma unroll
    for (int r = 0; r < 16; r++) {
        float mu = st[isK*64 + r0 + r], rs = rs_sh[isK*64 + r0 + r];
        outp[(base + r0 + r)*E + col] = (qk[(r0 + r)*128 + isK*64 + col] - mu) * rs * gg + bb;
    }
}

// ============================================================
// Kernel 2: flash attention (no running max: q,k are LN'd -> scores bounded)
// BR=64 rows/CTA, 512 threads, 1 CTA/SM.
// PV layout: rgV=tid>>6 (8 rows each), cgV=tid&63 (6 cols each) -> acc 8x6.
// S layout:  rgS=tid>>5 (4 rows each), cgS=tid&31 (m index).
// Triple-buffered cp.async prefetch of K/V tiles.
// ============================================================
__device__ __forceinline__ void prefetch_tile(float* sm, int tid, int t,
        const float4* k1p4, const float4* nrm4)
{
    if (t < NT) {
        int s = t - (t/3)*3;
        int m0 = t * BCC;
        float* kd = sm + O_K + s*(BCC*KST);
        float* vd = sm + O_V + s*(BCC*VST);
        {   // K: 512 float4, one per thread
            int mm = tid >> 4, j4 = tid & 15;
            int g = m0 + mm; if (g >= NN) g = NN - 1;
            cpa16(smaddr(kd + mm*KST + j4*4), k1p4 + (size_t)g*16 + j4);
        }
#pragma unroll
        for (int i = 0; i < 6; i++) {   // V: 3072 float4
            int idx = tid + i*512;
            int mm = idx / 96, c4 = idx - mm*96;
            int g = m0 + mm; if (g >= NN) g = NN - 1;
            cpa16(smaddr(vd + mm*VST + c4*4), nrm4 + (size_t)g*96 + c4);
        }
    }
    asm volatile("cp.async.commit_group;");
}

__global__ __launch_bounds__(512, 1) void attn_kernel(
    const float* __restrict__ x,
    const float* __restrict__ normal,
    const float* __restrict__ Win,
    float* __restrict__ out)
{
    extern __shared__ float sm[];
    const int tid = threadIdx.x;
    const int b   = blockIdx.y;
    const int n0  = blockIdx.x * BRR;
    const int rgV = tid >> 6, cgV = tid & 63, rbV = rgV*8;
    const int rgS = tid >> 5, cgS = tid & 31, rbS = rgS*4;

    const float4* q1p4 = (const float4*)(g_q1 + (size_t)b*NN*E);
    const float4* k1p4 = (const float4*)(g_k1 + (size_t)b*NN*E);
    const float4* nrm4 = (const float4*)normal;

    // load q tile (clamped rows; padded rows harmless, stores guarded)
#pragma unroll
    for (int i = 0; i < 2; i++) {
        int idx = tid + i*512;
        int r = idx >> 4, j4 = idx & 15;
        int g = n0 + r; if (g >= NN) g = NN - 1;
        ((float4*)(sm + O_Q))[idx] = q1p4[(size_t)g*16 + j4];
    }
    prefetch_tile(sm, tid, 0, k1p4, nrm4);
    prefetch_tile(sm, tid, 1, k1p4, nrm4);

    u64 acc[8][3];
#pragma unroll
    for (int r = 0; r < 8; r++)
#pragma unroll
        for (int c = 0; c < 3; c++) acc[r][c] = 0ull;
    float lacc[4];
#pragma unroll
    for (int r = 0; r < 4; r++) lacc[r] = 0.f;

    u64* p_u = (u64*)(sm + O_P);
    const float scale = 0.022360679774997897f;   // 1/sqrt(2000)

    for (int t = 0; t < NT; t++) {
        int s = t - (t/3)*3;
        asm volatile("cp.async.wait_group 1;");
        __syncthreads();

        // ---- S = q.k, exp, store p (duplicated pairs) ----
        {
            const ulonglong2* kk = (const ulonglong2*)(sm + O_K + s*(BCC*KST) + cgS*KST);
            u64 dacc[4];
#pragma unroll
            for (int r = 0; r < 4; r++) dacc[r] = 0ull;
#pragma unroll
            for (int j2 = 0; j2 < 16; j2++) {
                ulonglong2 kv = kk[j2];
#pragma unroll
                for (int r = 0; r < 4; r++) {
                    ulonglong2 qv = ((const ulonglong2*)(sm + O_Q + (rbS + r)*E))[j2];
                    ffma2(dacc[r], qv.x, kv.x);
                    ffma2(dacc[r], qv.y, kv.y);
                }
            }
            const bool mval = (t*BCC + cgS) < NN;
            u64 pp[4];
#pragma unroll
            for (int r = 0; r < 4; r++) {
                float2 f = unpack2(dacc[r]);
                float p = mval ? __expf((f.x + f.y) * scale) : 0.f;
                lacc[r] += p;
                pp[r] = pack2(p, p);
            }
            ulonglong2* ps = (ulonglong2*)(p_u + cgS*PST + rbS);
            ulonglong2 w0; w0.x = pp[0]; w0.y = pp[1]; ps[0] = w0;
            ulonglong2 w1; w1.x = pp[2]; w1.y = pp[3]; ps[1] = w1;
        }
        __syncthreads();
        prefetch_tile(sm, tid, t + 2, k1p4, nrm4);

        // ---- PV: acc[8 rows][6 cols] += p * v ----
        {
            const float* vb = sm + O_V + s*(BCC*VST) + cgV*6;
#pragma unroll 4
            for (int m = 0; m < BCC; m++) {
                const u64* vv = (const u64*)(vb + m*VST);
                u64 v0 = vv[0], v1 = vv[1], v2 = vv[2];
                const ulonglong2* pl = (const ulonglong2*)(p_u + m*PST + rbV);  // broadcast
                ulonglong2 pA = pl[0], pB = pl[1], pC = pl[2], pD = pl[3];
                u64 pr[8] = {pA.x, pA.y, pB.x, pB.y, pC.x, pC.y, pD.x, pD.y};
#pragma unroll
                for (int r = 0; r < 8; r++) {
                    ffma2(acc[r][0], pr[r], v0);
                    ffma2(acc[r][1], pr[r], v1);
                    ffma2(acc[r][2], pr[r], v2);
                }
            }
        }
    }

    // ---- l: reduce across 32 lanes (warp shares rows in S layout) ----
#pragma unroll
    for (int r = 0; r < 4; r++) {
#pragma unroll
        for (int off = 16; off; off >>= 1)
            lacc[r] += __shfl_xor_sync(0xffffffffu, lacc[r], off);
    }
    if ((tid & 31) == 0) {
        float* l_s = sm + O_L;
#pragma unroll
        for (int r = 0; r < 4; r++) l_s[rbS + r] = lacc[r];
    }
    __syncthreads();   // l_s ready AND all PV reads of V buffers done

    // ---- stage data = acc / l (reuse V area, stride OST) ----
    float* stage = sm + O_V;
    {
        const float* l_s = sm + O_L;
#pragma unroll
        for (int r = 0; r < 8; r++) {
            float inv = 1.f / l_s[rbV + r];
            float2 a0 = unpack2(acc[r][0]);
            float2 a1 = unpack2(acc[r][1]);
            float2 a2 = unpack2(acc[r][2]);
            float* dst = stage + (rbV + r)*OST + cgV*6;
            dst[0] = a0.x*inv; dst[1] = a0.y*inv;
            dst[2] = a1.x*inv; dst[3] = a1.y*inv;
            dst[4] = a2.x*inv; dst[5] = a2.y*inv;
        }
    }
    __syncthreads();

    // ---- RPPsAtt weights (per row) ----
    float* w_s = sm + O_P;   // reuse p area (64*24 floats)
    if (tid < BRR) {
        int n = n0 + tid;
        if (n < NN) {
            const float* xl = x + ((size_t)b*NN + n)*TD + (TT - 1)*DD;
            float q16[DD];
#pragma unroll
            for (int dp = 0; dp < DD; dp++) {
                float sacc = 0.f;
#pragma unroll
                for (int d = 0; d < DD; d++) sacc += xl[d] * Win[d*DD + dp];
                q16[dp] = sacc;
            }
            const float* row = stage + tid*OST;
            float att[TT]; float mx = -1e30f;
#pragma unroll
            for (int tt2 = 0; tt2 < TT; tt2++) {
                float sacc = 0.f;
#pragma unroll
                for (int d = 0; d < DD; d++) sacc += q16[d] * row[tt2*DD + d];
                att[tt2] = sacc; mx = fmaxf(mx, sacc);
            }
            float se = 0.f;
#pragma unroll
            for (int tt2 = 0; tt2 < TT; tt2++) { float e = __expf(att[tt2] - mx); att[tt2] = e; se += e; }
            float si = 1.f / se;
#pragma unroll
            for (int tt2 = 0; tt2 < TT; tt2++) w_s[tid*TT + tt2] = att[tt2] * si;
        }
    }
    __syncthreads();

    // ---- out = data + weight[..., None] ----
    int nrows = NN - n0; if (nrows > BRR) nrows = BRR;
    float4* outp = (float4*)(out + ((size_t)b*NN + n0)*TD);
    for (int i = tid; i < nrows*96; i += 512) {
        int r = i / 96, c4 = i - r*96;
        float4 v = ((const float4*)stage)[r*OST4 + c4];
        float w = w_s[r*TT + (c4 >> 2)];
        v.x += w; v.y += w; v.z += w; v.w += w;
        outp[i] = v;
    }
}

// ============================================================
extern "C" void kernel_launch(void* const* d_in, const int* in_sizes, int n_in,
                              void* d_out, int out_size)
{
    (void)in_sizes; (void)n_in; (void)out_size;
    const float* x     = (const float*)d_in[0];
    const float* Wq    = (const float*)d_in[1];
    const float* bq    = (const float*)d_in[2];
    const float* Wk    = (const float*)d_in[3];
    const float* bk    = (const float*)d_in[4];
    const float* g0    = (const float*)d_in[5];
    const float* beta0 = (const float*)d_in[6];
    const float* g1    = (const float*)d_in[7];
    const float* beta1 = (const float*)d_in[8];
    const float* nrm   = (const float*)d_in[9];
    const float* Win   = (const float*)d_in[10];
    float* out = (float*)d_out;

    cudaFuncSetAttribute(qk_ln_kernel, cudaFuncAttributeMaxDynamicSharedMemorySize, K1_SM_BYTES);
    cudaFuncSetAttribute(attn_kernel,  cudaFuncAttributeMaxDynamicSharedMemorySize, SM_BYTES);

    qk_ln_kernel<<<(B*NN)/K1_ROWS, 512, K1_SM_BYTES>>>(x, Wq, bq, Wk, bk, g0, beta0, g1, beta1);

    dim3 grid((NN + BRR - 1)/BRR, B);
    attn_kernel<<<grid, 512, SM_BYTES>>>(x, nrm, Win, out);
}